// round 15
// baseline (speedup 1.0000x reference)
#include <cuda_runtime.h>
#include <cstdint>
#include <cstring>

#define NB 256   // batch
#define NPTS 256 // points per side (N == M)
#define ND 4

// per-batch results: [0..NB): eucl_non_zero, [NB..2NB): eucl_zero
__device__ float g_part[2 * NB];
__device__ int   g_count = 0;

static __device__ __forceinline__ uint64_t dup2(float v) {
    uint64_t r; asm("mov.b64 %0, {%1, %1};" : "=l"(r) : "f"(v)); return r;
}
static __device__ __forceinline__ uint64_t ffma2(uint64_t a, uint64_t b, uint64_t c) {
    uint64_t d; asm("fma.rn.f32x2 %0, %1, %2, %3;" : "=l"(d) : "l"(a), "l"(b), "l"(c)); return d;
}
static __device__ __forceinline__ uint64_t add2(uint64_t a, uint64_t b) {
    uint64_t d; asm("add.rn.f32x2 %0, %1, %2;" : "=l"(d) : "l"(a), "l"(b)); return d;
}
static __device__ __forceinline__ float2 asf2(uint64_t v) {
    float2 f; memcpy(&f, &v, 8); return f;   // register-pair aliasing, no SASS op
}

__global__ __launch_bounds__(256) void chamfer_kernel(
    const float* __restrict__ target,
    const float* __restrict__ reco,
    const int*   __restrict__ in_pid,
    const int*   __restrict__ out_pid,
    float*       __restrict__ out)
{
    // reco tile, pair-interleaved for f32x2 (pair p = cols 2p, 2p+1)
    __shared__ ulonglong2 cA[NPTS/2], cB[NPTS/2];
    __shared__ uint64_t   cC[NPTS/2];               // n2y + peny (packed)
    __shared__ float4     rowsm[NPTS];              // target rows
    __shared__ float      rowc[NPTS];               // n2x + penx
    __shared__ int        rmasks[NPTS];             // mask_x
    __shared__ int        cmasks[NPTS];             // mask_y
    __shared__ float      rowred[NPTS * 17];        // [row][tj] partial row-mins
    __shared__ float      colred[16 * 272];         // [ti][col] partial col-mins
    __shared__ float4     swred[8];
    __shared__ int        s_last;

    const int b  = blockIdx.x;
    const int t  = threadIdx.x;
    const int ti = t >> 4;     // rows [ti*16, ti*16+16)
    const int tj = t & 15;     // cols [tj*16, tj*16+16) = pairs [tj*8, +8)

    const float4* tg4 = (const float4*)(target + (size_t)b * NPTS * ND);
    const float4* rc4 = (const float4*)(reco   + (size_t)b * NPTS * ND);
    const int*    ip  = in_pid  + b * NPTS;
    const int*    op  = out_pid + b * NPTS;

    // ---- prologue: each thread loads 1 target pt + 1 reco pt ----
    float4 tv = tg4[t];
    float4 rv = rc4[t];
    int    tp = ip[t];
    int    rp = op[t];

    const float n2x = tv.x*tv.x + tv.y*tv.y + tv.z*tv.z + tv.w*tv.w;
    const float n2y = rv.x*rv.x + rv.y*rv.y + rv.z*rv.z + rv.w*rv.w;

    {
        int pair = t >> 1, lane = t & 1;
        ((float*)cA)[pair*4 + lane]     = -2.0f * rv.x;
        ((float*)cA)[pair*4 + 2 + lane] = -2.0f * rv.y;
        ((float*)cB)[pair*4 + lane]     = -2.0f * rv.z;
        ((float*)cB)[pair*4 + 2 + lane] = -2.0f * rv.w;
        ((float*)cC)[t] = n2y + (rp != 0 ? 0.0f : 1e20f);
        rowsm[t]  = tv;
        rowc[t]   = n2x + (tp != 0 ? 0.0f : 1e20f);
        rmasks[t] = (tp != 0);
        cmasks[t] = (rp != 0);
    }

    // per-thread norm contributions for edge cases
    float c_nrmx  = (tp != 0) ? sqrtf(n2x) : 0.0f;  // sum ||x|| over mask_x
    float c_nrmy0 = (rp != 0) ? 0.0f : sqrtf(n2y);  // sum ||y|| over ~mask_y

    const int nx = __syncthreads_count(tp != 0);
    const int ny = __syncthreads_count(rp != 0);

    // ---- cache this thread's 8 col-pairs in registers ----
    ulonglong2 A[8], Bv[8];
    uint64_t   C[8];
    #pragma unroll
    for (int k = 0; k < 8; ++k) {
        A[k]  = cA[tj*8 + k];
        Bv[k] = cB[tj*8 + k];
        C[k]  = cC[tj*8 + k];
    }

    float colLo[8], colHi[8];
    #pragma unroll
    for (int k = 0; k < 8; ++k) { colLo[k] = 3.0e38f; colHi[k] = 3.0e38f; }

    // ---- main loop: 16 rows x 8 col-pairs; each d2 feeds BOTH directions ----
    #pragma unroll 4
    for (int r16 = 0; r16 < 16; ++r16) {
        const int row = ti * 16 + r16;
        float4 x = rowsm[row];                    // broadcast
        const uint64_t rxx = dup2(x.x), rxy = dup2(x.y);
        const uint64_t rxz = dup2(x.z), rxw = dup2(x.w);
        const uint64_t rc2 = dup2(rowc[row]);
        float r0 = 3.0e38f, r1 = 3.0e38f;         // two interleaved row-min chains
        #pragma unroll
        for (int k = 0; k < 8; ++k) {
            uint64_t s = ffma2(A[k].x, rxx, C[k]);
            s = ffma2(A[k].y, rxy, s);
            s = ffma2(Bv[k].x, rxz, s);
            s = ffma2(Bv[k].y, rxw, s);
            s = add2(s, rc2);                     // full d^2 (+both pens), packed
            float2 f = asf2(s);
            colLo[k] = fminf(colLo[k], f.x);
            colHi[k] = fminf(colHi[k], f.y);
            if (k & 1) r1 = fminf(r1, fminf(f.x, f.y));
            else       r0 = fminf(r0, fminf(f.x, f.y));
        }
        rowred[row * 17 + tj] = fminf(r0, r1);    // 1 STS, conflict-free (17-stride)
    }

    // ---- store col partials: [ti][col], 4x STS.128 ----
    {
        float4* dst = (float4*)(colred + ti * 272);
        #pragma unroll
        for (int j = 0; j < 4; ++j)
            dst[tj * 4 + j] = make_float4(colLo[2*j], colHi[2*j], colLo[2*j+1], colHi[2*j+1]);
    }
    __syncthreads();

    // ---- final: thread t owns row t and col t ----
    float rmin = rowred[t * 17];
    #pragma unroll
    for (int w = 1; w < 16; ++w) rmin = fminf(rmin, rowred[t * 17 + w]);
    float cmin = colred[t];
    #pragma unroll
    for (int w = 1; w < 16; ++w) cmin = fminf(cmin, colred[w * 272 + t]);

    float sum_x = rmasks[t] ? sqrtf(fmaxf(rmin, 0.0f)) : 0.0f;  // min_xy contribution
    float sum_y = cmasks[t] ? sqrtf(fmaxf(cmin, 0.0f)) : 0.0f;  // min_yx contribution

    // ---- warp shfl reduce of 4 sums ----
    #pragma unroll
    for (int off = 16; off > 0; off >>= 1) {
        sum_x   += __shfl_xor_sync(0xffffffffu, sum_x, off);
        sum_y   += __shfl_xor_sync(0xffffffffu, sum_y, off);
        c_nrmx  += __shfl_xor_sync(0xffffffffu, c_nrmx, off);
        c_nrmy0 += __shfl_xor_sync(0xffffffffu, c_nrmy0, off);
    }
    const int wid = t >> 5, lane = t & 31;
    if (lane == 0) swred[wid] = make_float4(sum_x, sum_y, c_nrmx, c_nrmy0);
    __syncthreads();

    // ---- thread 0: per-batch outputs ----
    if (t == 0) {
        float sum_xy = 0.0f, sum_yx = 0.0f, sum_nrmx = 0.0f, sum_nrmy0 = 0.0f;
        #pragma unroll
        for (int w = 0; w < 8; ++w) {
            float4 r = swred[w];
            sum_xy += r.x; sum_yx += r.y; sum_nrmx += r.z; sum_nrmy0 += r.w;
        }
        float n_in  = (float)max(1, nx);
        float n_out = (float)max(1, ny);
        float normal = 0.5f * (sum_xy / n_out + sum_yx / n_in);
        float e_nz = (ny == 0) ? (sum_nrmx / n_in)
                   : ((nx == 0) ? 0.0f : normal);
        float e_z  = sum_nrmy0 / (float)max(1, NPTS - ny);
        g_part[b]      = e_nz;
        g_part[NB + b] = e_z;
        __threadfence();
        int old = atomicAdd(&g_count, 1);
        s_last = (old == NB - 1);
    }
    __syncthreads();

    // ---- last block: mean over batches (1 batch per thread) ----
    if (s_last) {
        if (t == 0) { g_count = 0; __threadfence(); }
        float e0 = __ldcg(&g_part[t]);
        float e1 = __ldcg(&g_part[NB + t]);
        #pragma unroll
        for (int off = 16; off > 0; off >>= 1) {
            e0 += __shfl_xor_sync(0xffffffffu, e0, off);
            e1 += __shfl_xor_sync(0xffffffffu, e1, off);
        }
        if (lane == 0) swred[wid] = make_float4(e0, e1, 0.0f, 0.0f);
        __syncthreads();
        if (t == 0) {
            float a = 0.0f, b2 = 0.0f;
            #pragma unroll
            for (int w = 0; w < 8; ++w) { a += swred[w].x; b2 += swred[w].y; }
            out[0] = a * (1.0f / NB);
            out[1] = b2 * (1.0f / NB);
        }
    }
}

extern "C" void kernel_launch(void* const* d_in, const int* in_sizes, int n_in,
                              void* d_out, int out_size)
{
    const float* target  = (const float*)d_in[0];
    const float* reco    = (const float*)d_in[1];
    const int*   in_pid  = (const int*)d_in[2];
    const int*   out_pid = (const int*)d_in[3];
    float* out = (float*)d_out;

    chamfer_kernel<<<NB, 256>>>(target, reco, in_pid, out_pid, out);
}

// round 16
// speedup vs baseline: 1.0171x; 1.0171x over previous
#include <cuda_runtime.h>
#include <cstdint>
#include <cstring>

#define NB 256
#define NPTS 256
#define ND 4

__device__ float g_part[2 * NB];
__device__ int   g_count = 0;

static __device__ __forceinline__ uint64_t dup2(float v) {
    uint64_t r; asm("mov.b64 %0, {%1, %1};" : "=l"(r) : "f"(v)); return r;
}
static __device__ __forceinline__ uint64_t ffma2(uint64_t a, uint64_t b, uint64_t c) {
    uint64_t d; asm("fma.rn.f32x2 %0, %1, %2, %3;" : "=l"(d) : "l"(a), "l"(b), "l"(c)); return d;
}
static __device__ __forceinline__ uint64_t add2(uint64_t a, uint64_t b) {
    uint64_t d; asm("add.rn.f32x2 %0, %1, %2;" : "=l"(d) : "l"(a), "l"(b)); return d;
}
static __device__ __forceinline__ float2 asf2(uint64_t v) {
    float2 f; memcpy(&f, &v, 8); return f;
}

__global__ __launch_bounds__(256) void chamfer_kernel(
    const float* __restrict__ target,
    const float* __restrict__ reco,
    const int*   __restrict__ in_pid,
    const int*   __restrict__ out_pid,
    float*       __restrict__ out)
{
    // reco cols, pair-interleaved for f32x2 (pair p = cols 2p,2p+1)
    __shared__ ulonglong2 cA[NPTS/2], cB[NPTS/2];
    __shared__ uint64_t   cC[NPTS/2];            // n2y + peny (packed)
    __shared__ uint64_t   rowd[NPTS * 6];        // per row: {x,x},{y,y},{z,z},{w,w},{n2x+penx dup}, pad
    __shared__ float      rowred[NPTS * 17];     // [row][tj] row-min partials
    __shared__ float      colred[16 * 264];      // [ti][col] col-min partials
    __shared__ float4     swred[8];
    __shared__ int        s_last;

    const int b  = blockIdx.x;
    const int t  = threadIdx.x;
    const int ti = t >> 4;     // rows [ti*16, ti*16+16)
    const int tj = t & 15;     // cols [tj*16, tj*16+16)

    const float4* tg4 = (const float4*)(target + (size_t)b * NPTS * ND);
    const float4* rc4 = (const float4*)(reco   + (size_t)b * NPTS * ND);
    const int*    ip  = in_pid  + b * NPTS;
    const int*    op  = out_pid + b * NPTS;

    // ---- prologue ----
    float4 tv = tg4[t];
    float4 rv = rc4[t];
    int    tp = ip[t];
    int    rp = op[t];

    const float n2x = tv.x*tv.x + tv.y*tv.y + tv.z*tv.z + tv.w*tv.w;
    const float n2y = rv.x*rv.x + rv.y*rv.y + rv.z*rv.z + rv.w*rv.w;

    {
        int pair = t >> 1, lane = t & 1;
        ((float*)cA)[pair*4 + lane]     = -2.0f * rv.x;
        ((float*)cA)[pair*4 + 2 + lane] = -2.0f * rv.y;
        ((float*)cB)[pair*4 + lane]     = -2.0f * rv.z;
        ((float*)cB)[pair*4 + 2 + lane] = -2.0f * rv.w;
        ((float*)cC)[t] = n2y + (rp != 0 ? 0.0f : 1e20f);
        rowd[t*6 + 0] = dup2(tv.x);
        rowd[t*6 + 1] = dup2(tv.y);
        rowd[t*6 + 2] = dup2(tv.z);
        rowd[t*6 + 3] = dup2(tv.w);
        rowd[t*6 + 4] = dup2(n2x + (tp != 0 ? 0.0f : 1e20f));
    }

    const int rmask = (tp != 0);   // thread t owns row t
    const int cmask = (rp != 0);   // thread t owns col t
    float c_nrmx  = rmask ? sqrtf(n2x) : 0.0f;
    float c_nrmy0 = cmask ? 0.0f : sqrtf(n2y);

    const int nx = __syncthreads_count(tp != 0);
    const int ny = __syncthreads_count(rp != 0);

    // ---- row-min partials in registers (16 rows of group ti, min over this thread's 16 cols) ----
    float rmin[16];
    #pragma unroll
    for (int r = 0; r < 16; ++r) rmin[r] = 3.0e38f;

    // ---- two passes of 4 cached col-pairs; each d2 serves BOTH directions ----
    #pragma unroll 1
    for (int p = 0; p < 2; ++p) {
        ulonglong2 A[4], Bv[4];
        uint64_t   C[4];
        #pragma unroll
        for (int k = 0; k < 4; ++k) {
            int idx = tj*8 + p*4 + k;
            A[k]  = cA[idx];
            Bv[k] = cB[idx];
            C[k]  = cC[idx];
        }
        float colLo[4], colHi[4];
        #pragma unroll
        for (int k = 0; k < 4; ++k) { colLo[k] = 3.0e38f; colHi[k] = 3.0e38f; }

        #pragma unroll
        for (int r = 0; r < 16; ++r) {
            const int row = ti * 16 + r;
            ulonglong2 d0 = *(const ulonglong2*)&rowd[row*6];      // {x,x},{y,y}
            ulonglong2 d1 = *(const ulonglong2*)&rowd[row*6 + 2];  // {z,z},{w,w}
            uint64_t  rc2 = rowd[row*6 + 4];                       // n2x+penx packed
            #pragma unroll
            for (int k = 0; k < 4; ++k) {
                uint64_t s = ffma2(A[k].x, d0.x, C[k]);
                s = ffma2(A[k].y, d0.y, s);
                s = ffma2(Bv[k].x, d1.x, s);
                s = ffma2(Bv[k].y, d1.y, s);
                s = add2(s, rc2);                 // full d^2 + both pens (packed)
                float2 f = asf2(s);
                colLo[k] = fminf(colLo[k], f.x);
                colHi[k] = fminf(colHi[k], f.y);
                rmin[r]  = fminf(rmin[r], fminf(f.x, f.y));
            }
        }

        // store this pass's col partials: cols tj*16 + p*8 + [0,8)
        float4* dst = (float4*)&colred[ti*264 + tj*16 + p*8];
        dst[0] = make_float4(colLo[0], colHi[0], colLo[1], colHi[1]);
        dst[1] = make_float4(colLo[2], colHi[2], colLo[3], colHi[3]);
    }

    // ---- store row partials (conflict-free: 17-stride) ----
    #pragma unroll
    for (int r = 0; r < 16; ++r)
        rowred[(ti*16 + r)*17 + tj] = rmin[r];
    __syncthreads();

    // ---- final: thread t owns row t and col t ----
    float rm = rowred[t*17];
    #pragma unroll
    for (int w = 1; w < 16; ++w) rm = fminf(rm, rowred[t*17 + w]);
    float cm = colred[t];
    #pragma unroll
    for (int w = 1; w < 16; ++w) cm = fminf(cm, colred[w*264 + t]);

    float sum_x = rmask ? sqrtf(fmaxf(rm, 0.0f)) : 0.0f;   // min_xy contribution
    float sum_y = cmask ? sqrtf(fmaxf(cm, 0.0f)) : 0.0f;   // min_yx contribution

    #pragma unroll
    for (int off = 16; off > 0; off >>= 1) {
        sum_x   += __shfl_xor_sync(0xffffffffu, sum_x, off);
        sum_y   += __shfl_xor_sync(0xffffffffu, sum_y, off);
        c_nrmx  += __shfl_xor_sync(0xffffffffu, c_nrmx, off);
        c_nrmy0 += __shfl_xor_sync(0xffffffffu, c_nrmy0, off);
    }
    const int wid = t >> 5, lane = t & 31;
    if (lane == 0) swred[wid] = make_float4(sum_x, sum_y, c_nrmx, c_nrmy0);
    __syncthreads();

    if (t == 0) {
        float sum_xy = 0.0f, sum_yx = 0.0f, sum_nrmx = 0.0f, sum_nrmy0 = 0.0f;
        #pragma unroll
        for (int w = 0; w < 8; ++w) {
            float4 r = swred[w];
            sum_xy += r.x; sum_yx += r.y; sum_nrmx += r.z; sum_nrmy0 += r.w;
        }
        float n_in  = (float)max(1, nx);
        float n_out = (float)max(1, ny);
        float normal = 0.5f * (sum_xy / n_out + sum_yx / n_in);
        float e_nz = (ny == 0) ? (sum_nrmx / n_in)
                   : ((nx == 0) ? 0.0f : normal);
        float e_z  = sum_nrmy0 / (float)max(1, NPTS - ny);
        g_part[b]      = e_nz;
        g_part[NB + b] = e_z;
        __threadfence();
        int old = atomicAdd(&g_count, 1);
        s_last = (old == NB - 1);
    }
    __syncthreads();

    // ---- last block: mean over batches ----
    if (s_last) {
        if (t == 0) { g_count = 0; __threadfence(); }
        float e0 = __ldcg(&g_part[t]);
        float e1 = __ldcg(&g_part[NB + t]);
        #pragma unroll
        for (int off = 16; off > 0; off >>= 1) {
            e0 += __shfl_xor_sync(0xffffffffu, e0, off);
            e1 += __shfl_xor_sync(0xffffffffu, e1, off);
        }
        if (lane == 0) swred[wid] = make_float4(e0, e1, 0.0f, 0.0f);
        __syncthreads();
        if (t == 0) {
            float a = 0.0f, b2 = 0.0f;
            #pragma unroll
            for (int w = 0; w < 8; ++w) { a += swred[w].x; b2 += swred[w].y; }
            out[0] = a * (1.0f / NB);
            out[1] = b2 * (1.0f / NB);
        }
    }
}

extern "C" void kernel_launch(void* const* d_in, const int* in_sizes, int n_in,
                              void* d_out, int out_size)
{
    const float* target  = (const float*)d_in[0];
    const float* reco    = (const float*)d_in[1];
    const int*   in_pid  = (const int*)d_in[2];
    const int*   out_pid = (const int*)d_in[3];
    float* out = (float*)d_out;

    chamfer_kernel<<<NB, 256>>>(target, reco, in_pid, out_pid, out);
}

// round 17
// speedup vs baseline: 1.1380x; 1.1189x over previous
#include <cuda_runtime.h>
#include <cstdint>
#include <cstring>

#define NB 256   // batch
#define NPTS 256 // points per side (N == M)
#define ND 4

// per-batch partials: [0]=sum_xy [1]=sum_nrmx [2]=nx [3]=sum_yx [4]=sum_nrmy0 [5]=ny
__device__ float g_sc[6 * NB];
__device__ int   g_count = 0;

static __device__ __forceinline__ uint64_t dup2(float v) {
    uint64_t r; asm("mov.b64 %0, {%1, %1};" : "=l"(r) : "f"(v)); return r;
}
static __device__ __forceinline__ uint64_t ffma2(uint64_t a, uint64_t b, uint64_t c) {
    uint64_t d; asm("fma.rn.f32x2 %0, %1, %2, %3;" : "=l"(d) : "l"(a), "l"(b), "l"(c)); return d;
}
static __device__ __forceinline__ float2 asf2(uint64_t v) {
    float2 f; memcpy(&f, &v, 8); return f;   // register-pair aliasing, no SASS op
}

__global__ __launch_bounds__(128, 4) void chamfer_kernel(
    const float* __restrict__ target,
    const float* __restrict__ reco,
    const int*   __restrict__ in_pid,
    const int*   __restrict__ out_pid,
    float*       __restrict__ out)
{
    // Full tile (256 pts = 128 pairs), pair-interleaved for f32x2:
    //  sA[p] = { (-2x_e0,-2x_e1), (-2y_e0,-2y_e1) }, sB = comps 2,3
    //  sc[p] = ( ||pt0||^2+pen0 , ||pt1||^2+pen1 )
    __shared__ ulonglong2 sA[NPTS/2], sB[NPTS/2];
    __shared__ uint64_t   sc[NPTS/2];
    __shared__ float      spm[2 * NPTS];   // partial row-mins per tile-half
    __shared__ float      srn2[NPTS];      // ||row||^2
    __shared__ int        smask[NPTS];     // row pid != 0
    __shared__ float4     red[128];
    __shared__ int        s_last;

    const int bid   = blockIdx.x;
    const int b     = bid >> 1;
    const int phase = bid & 1;   // 0: rows=target, tile=reco ; 1: rows=reco, tile=target
    const int t     = threadIdx.x;
    const int q     = t & 63;
    const int half  = t >> 6;    // which tile half this thread scans

    const float* tileSrc = phase == 0 ? reco    : target;
    const int*   tilePid = phase == 0 ? out_pid : in_pid;
    const float* rowSrc  = phase == 0 ? target  : reco;
    const int*   rowPid  = phase == 0 ? in_pid  : out_pid;

    const float4* tile4 = (const float4*)(tileSrc + (size_t)b * NPTS * ND);
    const float4* row4  = (const float4*)(rowSrc  + (size_t)b * NPTS * ND);
    const int*    tpid  = tilePid + b * NPTS;
    const int*    rpid  = rowPid  + b * NPTS;

    // ---- build tile (2 points per thread) ----
    #pragma unroll
    for (int k = 0; k < 2; ++k) {
        int i = t + k * 128;
        float4 v = tile4[i];
        int pid  = tpid[i];
        float n2 = v.x*v.x + v.y*v.y + v.z*v.z + v.w*v.w;
        int pair = i >> 1, lane = i & 1;
        ((float*)sA)[pair*4 + lane]     = -2.0f * v.x;
        ((float*)sA)[pair*4 + 2 + lane] = -2.0f * v.y;
        ((float*)sB)[pair*4 + lane]     = -2.0f * v.z;
        ((float*)sB)[pair*4 + 2 + lane] = -2.0f * v.w;
        ((float*)sc)[i] = n2 + (pid != 0 ? 0.0f : 1e20f);
    }

    // ---- own 4 rows: row = q + 64k (coalesced per k; both halves load same rows) ----
    uint64_t rx[4], ry[4], rz[4], rw[4];
    #pragma unroll
    for (int k = 0; k < 4; ++k) {
        int row = q + 64 * k;
        float4 v = row4[row];
        rx[k] = dup2(v.x); ry[k] = dup2(v.y); rz[k] = dup2(v.z); rw[k] = dup2(v.w);
        if (half == 0) {
            float n2 = v.x*v.x + v.y*v.y + v.z*v.z + v.w*v.w;
            srn2[row]  = n2;
            smask[row] = (rpid[row] != 0);
        }
    }

    __syncthreads();

    // ---- main loop: 64 pair-iters over this thread's tile half, 4 rows -> 8 dist/iter ----
    float dlo0 = 3.0e38f, dhi0 = 3.0e38f, dlo1 = 3.0e38f, dhi1 = 3.0e38f;
    float dlo2 = 3.0e38f, dhi2 = 3.0e38f, dlo3 = 3.0e38f, dhi3 = 3.0e38f;
    const int mbase = half * 64;
    #pragma unroll 8
    for (int mm = 0; mm < 64; ++mm) {
        int m = mbase + mm;
        ulonglong2 A = sA[m];      // broadcast LDS.128
        ulonglong2 B = sB[m];      // broadcast LDS.128
        uint64_t   c = sc[m];      // broadcast LDS.64

        uint64_t s0 = ffma2(A.x, rx[0], c);
        uint64_t s1 = ffma2(A.x, rx[1], c);
        uint64_t s2 = ffma2(A.x, rx[2], c);
        uint64_t s3 = ffma2(A.x, rx[3], c);
        s0 = ffma2(A.y, ry[0], s0);
        s1 = ffma2(A.y, ry[1], s1);
        s2 = ffma2(A.y, ry[2], s2);
        s3 = ffma2(A.y, ry[3], s3);
        s0 = ffma2(B.x, rz[0], s0);
        s1 = ffma2(B.x, rz[1], s1);
        s2 = ffma2(B.x, rz[2], s2);
        s3 = ffma2(B.x, rz[3], s3);
        s0 = ffma2(B.y, rw[0], s0);
        s1 = ffma2(B.y, rw[1], s1);
        s2 = ffma2(B.y, rw[2], s2);
        s3 = ffma2(B.y, rw[3], s3);

        float2 f0 = asf2(s0), f1 = asf2(s1), f2 = asf2(s2), f3 = asf2(s3);
        dlo0 = fminf(dlo0, f0.x); dhi0 = fminf(dhi0, f0.y);
        dlo1 = fminf(dlo1, f1.x); dhi1 = fminf(dhi1, f1.y);
        dlo2 = fminf(dlo2, f2.x); dhi2 = fminf(dhi2, f2.y);
        dlo3 = fminf(dlo3, f3.x); dhi3 = fminf(dhi3, f3.y);
    }

    // ---- store partial mins for this tile half ----
    spm[half * NPTS + q]       = fminf(dlo0, dhi0);
    spm[half * NPTS + q + 64]  = fminf(dlo1, dhi1);
    spm[half * NPTS + q + 128] = fminf(dlo2, dhi2);
    spm[half * NPTS + q + 192] = fminf(dlo3, dhi3);
    __syncthreads();

    // ---- combine halves: thread t handles rows t and t+128 ----
    const int ra = t, rb = t + 128;
    float da = fmaxf(fminf(spm[ra], spm[NPTS + ra]) + srn2[ra], 0.0f);
    float db = fmaxf(fminf(spm[rb], spm[NPTS + rb]) + srn2[rb], 0.0f);
    const int ma = smask[ra], mb = smask[rb];

    float sum_min = (ma ? sqrtf(da) : 0.0f) + (mb ? sqrtf(db) : 0.0f);
    float na = sqrtf(srn2[ra]), nbn = sqrtf(srn2[rb]);
    float sum_nrm;
    if (phase == 0)   // sum ||x|| over mask_x
        sum_nrm = (ma ? na : 0.0f) + (mb ? nbn : 0.0f);
    else              // sum ||y|| over ~mask_y
        sum_nrm = (ma ? 0.0f : na) + (mb ? 0.0f : nbn);
    float cnt = (float)(ma + mb);   // nx (phase 0) or ny (phase 1)

    // ---- block tree reduction ----
    red[t] = make_float4(sum_min, sum_nrm, cnt, 0.0f);
    __syncthreads();
    #pragma unroll
    for (int s = 64; s > 0; s >>= 1) {
        if (t < s) {
            float4 a = red[t], cc = red[t + s];
            a.x += cc.x; a.y += cc.y; a.z += cc.z;
            red[t] = a;
        }
        __syncthreads();
    }

    if (t == 0) {
        float4 r = red[0];
        g_sc[(phase*3 + 0) * NB + b] = r.x;
        g_sc[(phase*3 + 1) * NB + b] = r.y;
        g_sc[(phase*3 + 2) * NB + b] = r.z;
        __threadfence();
        int old = atomicAdd(&g_count, 1);
        s_last = (old == 2*NB - 1);
    }
    __syncthreads();

    // ---- last block: fused finalize ----
    if (s_last) {
        if (t == 0) { g_count = 0; __threadfence(); }
        __syncthreads();
        float acc0 = 0.0f, acc1 = 0.0f;
        #pragma unroll
        for (int k = 0; k < 2; ++k) {
            int bb = t + k * 128;
            float sum_xy    = __ldcg(&g_sc[0*NB + bb]);
            float sum_nrmx  = __ldcg(&g_sc[1*NB + bb]);
            float fnx       = __ldcg(&g_sc[2*NB + bb]);
            float sum_yx    = __ldcg(&g_sc[3*NB + bb]);
            float sum_nrmy0 = __ldcg(&g_sc[4*NB + bb]);
            float fny       = __ldcg(&g_sc[5*NB + bb]);
            float n_in  = fmaxf(1.0f, fnx);
            float n_out = fmaxf(1.0f, fny);
            float normal = 0.5f * (sum_xy / n_out + sum_yx / n_in);
            float e_nz = (fny == 0.0f) ? (sum_nrmx / n_in)
                       : ((fnx == 0.0f) ? 0.0f : normal);
            float e_z  = sum_nrmy0 / fmaxf(1.0f, (float)NPTS - fny);
            acc0 += e_nz;
            acc1 += e_z;
        }
        red[t] = make_float4(acc0, acc1, 0.0f, 0.0f);
        __syncthreads();
        #pragma unroll
        for (int s = 64; s > 0; s >>= 1) {
            if (t < s) {
                float4 a = red[t], cc = red[t + s];
                a.x += cc.x; a.y += cc.y;
                red[t] = a;
            }
            __syncthreads();
        }
        if (t == 0) {
            out[0] = red[0].x * (1.0f / NB);
            out[1] = red[0].y * (1.0f / NB);
        }
    }
}

extern "C" void kernel_launch(void* const* d_in, const int* in_sizes, int n_in,
                              void* d_out, int out_size)
{
    const float* target  = (const float*)d_in[0];
    const float* reco    = (const float*)d_in[1];
    const int*   in_pid  = (const int*)d_in[2];
    const int*   out_pid = (const int*)d_in[3];
    float* out = (float*)d_out;

    chamfer_kernel<<<2 * NB, 128>>>(target, reco, in_pid, out_pid, out);
}